// round 8
// baseline (speedup 1.0000x reference)
#include <cuda_runtime.h>
#include <cuda_bf16.h>

// Problem shapes:
//   node_emb      [100000, 64] f32
//   hyperedge_emb [ 50000, 64] f32
//   h             [200000]      i32
//   X             [200000, 8]   i32
//   out           [200000, 2]   f32
//
// Layout: 16 lanes per candidate (lane owns one float4 = 4 dims, held as a
// ulonglong2 so packed f32x2 pairs come straight out of LDG.128),
// 2 candidates per warp, 128 threads/block.
// Dot products use Blackwell packed f32x2 FMA. Cross-lane sums use
// recursive-halving reduce-scatter (15 shuffles / 16-value group); the
// induced bit-reversal permutation is harmless since every group feeds a
// min. X row loaded as 2x int4 (uniform within segment -> L1 broadcast).
// Registers capped at 56 (launch_bounds occ=9) -> 36 warps/SM.

#define SET_SIZE 8
#define EMB_DIM  64
#define ROW_BYTES 256
#define FULL 0xffffffffu
#define PAD_BIG 1e30f

typedef unsigned long long u64;

__device__ __forceinline__ u64 mul2(u64 a, u64 b) {
    u64 r;
    asm("mul.rn.f32x2 %0, %1, %2;" : "=l"(r) : "l"(a), "l"(b));
    return r;
}
__device__ __forceinline__ u64 fma2(u64 a, u64 b, u64 c) {
    u64 r;
    asm("fma.rn.f32x2 %0, %1, %2, %3;" : "=l"(r) : "l"(a), "l"(b), "l"(c));
    return r;
}

// dot of two 4-dim slices held as packed f32x2 pairs: 2 packed ops + 1 FADD.
__device__ __forceinline__ float dot4p(const ulonglong2& a, const ulonglong2& b) {
    u64 p = mul2(a.x, b.x);
    p = fma2(a.y, b.y, p);
    float lo = __uint_as_float((unsigned)p);
    float hi = __uint_as_float((unsigned)(p >> 32));
    return lo + hi;
}

__device__ __forceinline__ float fast_sigmoid(float x) {
    return 1.0f / (1.0f + __expf(-x));
}

__device__ __forceinline__ ulonglong2 ldg16_off(const char* base, unsigned byte_off) {
    return __ldg(reinterpret_cast<const ulonglong2*>(base + byte_off));
}

// Reduce-scatter 16 values across the 16-lane segment (sub = lane & 15).
// Afterwards each lane holds the full 16-lane sum of value index bitrev4(sub).
__device__ __forceinline__ float rs16(float (&cur)[16], int sub) {
    #pragma unroll
    for (int j = 0; j < 8; j++) {
        float send = (sub & 1) ? cur[j] : cur[j + 8];
        float keep = (sub & 1) ? cur[j + 8] : cur[j];
        cur[j] = keep + __shfl_xor_sync(FULL, send, 1);
    }
    #pragma unroll
    for (int j = 0; j < 4; j++) {
        float send = (sub & 2) ? cur[j] : cur[j + 4];
        float keep = (sub & 2) ? cur[j + 4] : cur[j];
        cur[j] = keep + __shfl_xor_sync(FULL, send, 2);
    }
    #pragma unroll
    for (int j = 0; j < 2; j++) {
        float send = (sub & 4) ? cur[j] : cur[j + 2];
        float keep = (sub & 4) ? cur[j + 2] : cur[j];
        cur[j] = keep + __shfl_xor_sync(FULL, send, 4);
    }
    {
        float send = (sub & 8) ? cur[0] : cur[1];
        float keep = (sub & 8) ? cur[1] : cur[0];
        cur[0] = keep + __shfl_xor_sync(FULL, send, 8);
    }
    return cur[0];
}

__global__ __launch_bounds__(128, 9)
void hyperedge_score_kernel(const float* __restrict__ node_emb,
                            const float* __restrict__ hyper_emb,
                            const int* __restrict__ h,
                            const int* __restrict__ X,
                            float* __restrict__ out,
                            int n_cand)
{
    const int lane = threadIdx.x & 31;
    const int warp = threadIdx.x >> 5;
    const int seg  = lane >> 4;   // candidate within warp (0..1)
    const int sub  = lane & 15;   // float4 slice id      (0..15)

    int e = (blockIdx.x * 4 + warp) * 2 + seg;
    int ec = min(e, n_cand - 1);

    // Each lane loads its candidate's full X row: 2x int4, uniform within
    // the 16-lane segment (L1 broadcast).
    const int4* xrow = reinterpret_cast<const int4*>(X + ec * SET_SIZE);
    int4 xa = __ldg(xrow);
    int4 xb = __ldg(xrow + 1);
    int h_idx = __ldg(h + ec);

    const char* nbase = reinterpret_cast<const char*>(node_emb);
    const char* hbase = reinterpret_cast<const char*>(hyper_emb);
    const unsigned lane_off = (unsigned)(sub * 16);   // float4 within row

    // Gather src slice + 8 node slices; all loads issued up front (MLP).
    ulonglong2 s = ldg16_off(hbase, (unsigned)h_idx * ROW_BYTES + lane_off);

    ulonglong2 nv[SET_SIZE];
    nv[0] = ldg16_off(nbase, (unsigned)xa.x * ROW_BYTES + lane_off);
    nv[1] = ldg16_off(nbase, (unsigned)xa.y * ROW_BYTES + lane_off);
    nv[2] = ldg16_off(nbase, (unsigned)xa.z * ROW_BYTES + lane_off);
    nv[3] = ldg16_off(nbase, (unsigned)xa.w * ROW_BYTES + lane_off);
    nv[4] = ldg16_off(nbase, (unsigned)xb.x * ROW_BYTES + lane_off);
    nv[5] = ldg16_off(nbase, (unsigned)xb.y * ROW_BYTES + lane_off);
    nv[6] = ldg16_off(nbase, (unsigned)xb.z * ROW_BYTES + lane_off);
    nv[7] = ldg16_off(nbase, (unsigned)xb.w * ROW_BYTES + lane_off);

    float cur[16];

    // ---- group 0: star (indices 0..7) + diagonal (indices 8..15) ----
    #pragma unroll
    for (int t = 0; t < SET_SIZE; t++) cur[t] = dot4p(s, nv[t]);
    #pragma unroll
    for (int t = 0; t < SET_SIZE; t++) cur[8 + t] = dot4p(nv[t], nv[t]);

    float v = rs16(cur, sub);
    // bitrev: even lanes hold star sums, odd lanes hold diagonal sums.
    v = fminf(v, __shfl_xor_sync(FULL, v, 2));
    v = fminf(v, __shfl_xor_sync(FULL, v, 4));
    v = fminf(v, __shfl_xor_sync(FULL, v, 8));
    float star_min = v;                               // valid on even lanes
    float diag_min = __shfl_xor_sync(FULL, v, 1);     // odd lanes' min, now on even

    // ---- off-diagonal pairs: 28 dots in 2 chunks of 16 ----
    {
        const int PA0[16] = {0,0,0,0,0,0,0, 1,1,1,1,1,1, 2,2,2};
        const int PB0[16] = {1,2,3,4,5,6,7, 2,3,4,5,6,7, 3,4,5};
        #pragma unroll
        for (int k = 0; k < 16; k++) cur[k] = dot4p(nv[PA0[k]], nv[PB0[k]]);
    }
    float p0 = rs16(cur, sub);

    {
        const int PA1[12] = {2,2, 3,3,3,3, 4,4,4, 5,5, 6};
        const int PB1[12] = {6,7, 4,5,6,7, 5,6,7, 6,7, 7};
        #pragma unroll
        for (int k = 0; k < 12; k++) cur[k] = dot4p(nv[PA1[k]], nv[PB1[k]]);
        #pragma unroll
        for (int k = 12; k < 16; k++) cur[k] = PAD_BIG;
    }
    float p1 = rs16(cur, sub);

    float pmin = fminf(p0, p1);
    pmin = fminf(pmin, __shfl_xor_sync(FULL, pmin, 1));
    pmin = fminf(pmin, __shfl_xor_sync(FULL, pmin, 2));
    pmin = fminf(pmin, __shfl_xor_sync(FULL, pmin, 4));
    pmin = fminf(pmin, __shfl_xor_sync(FULL, pmin, 8));

    if (e < n_cand && sub == 0) {
        float clique = fminf(diag_min, pmin);
        float2 o = make_float2(fast_sigmoid(star_min), fast_sigmoid(clique));
        reinterpret_cast<float2*>(out)[e] = o;
    }
}

extern "C" void kernel_launch(void* const* d_in, const int* in_sizes, int n_in,
                              void* d_out, int out_size) {
    const float* node_emb  = (const float*)d_in[0];
    const float* hyper_emb = (const float*)d_in[1];
    const int*   h         = (const int*)d_in[2];
    const int*   X         = (const int*)d_in[3];
    float*       out       = (float*)d_out;

    const int n_cand = in_sizes[2];

    const int cands_per_block = 8;    // 4 warps * 2 candidates
    const int blocks = (n_cand + cands_per_block - 1) / cands_per_block;

    hyperedge_score_kernel<<<blocks, 128>>>(node_emb, hyper_emb, h, X, out, n_cand);
}